// round 1
// baseline (speedup 1.0000x reference)
#include <cuda_runtime.h>

#define BB 16
#define QN 128
#define KN 512
#define HN 128
#define DD 128

// scratch: k_proj transposed  [b][h][k]  (4 MB)
__device__ float g_kpt[BB * HN * KN];

__device__ __forceinline__ float ex2f(float x) {
    float r; asm("ex2.approx.f32 %0, %1;" : "=f"(r) : "f"(x)); return r;
}
__device__ __forceinline__ float rcpf(float x) {
    float r; asm("rcp.approx.f32 %0, %1;" : "=f"(r) : "f"(x)); return r;
}

// ---------------------------------------------------------------------------
// Kernel A: g_kpt[b][h][k] = sum_d keys[b][k][d] * Wk[d][h]
// Block = (k-tile of 32 keys, b). 256 threads. Transpose via smem tile so the
// [h][k] store is coalesced.
// ---------------------------------------------------------------------------
__global__ __launch_bounds__(256) void kproj_kernel(
    const float* __restrict__ keys, const float* __restrict__ Wk)
{
    __shared__ float skeys[32][DD];     // 16 KB
    __shared__ float stile[HN][33];     // padded transpose tile

    const int b  = blockIdx.y;
    const int k0 = blockIdx.x * 32;
    const int tid = threadIdx.x;

    for (int i = tid; i < 32 * DD; i += 256) {
        int kk = i >> 7, d = i & 127;
        skeys[kk][d] = keys[(b * KN + k0 + kk) * DD + d];
    }
    __syncthreads();

    for (int o = tid; o < 32 * HN; o += 256) {
        int kk = o >> 7, h = o & 127;       // within a warp: kk const, h consecutive
        float acc = 0.f;
        #pragma unroll 8
        for (int d = 0; d < DD; d++)
            acc = fmaf(skeys[kk][d], Wk[d * HN + h], acc);
        stile[h][kk] = acc;
    }
    __syncthreads();

    for (int o = tid; o < HN * 32; o += 256) {
        int h = o >> 5, kk = o & 31;        // 32 consecutive k per warp -> coalesced
        g_kpt[(b * HN + h) * KN + k0 + kk] = stile[h][kk];
    }
}

// ---------------------------------------------------------------------------
// Kernel B: one block per (b, q). 512 threads.
//   phase 0: load q row + w_v, fused q-projection, precompute folded constants
//   phase 1: thread k computes score_k = sum_h wv[h]*tanh(qh[h]+kpt[h][k])
//            folded as: score = sum(wv) - sum_h (2*wv[h]) * rcp(1 + ex2(2x*log2e))
//   phase 1.5: masked softmax over 512 keys (block reduction)
//   phase 2: out[v] = sum_k attn[k]*values[b][k][v], 4-way split over k
// ---------------------------------------------------------------------------
__global__ __launch_bounds__(512) void attn_kernel(
    const float* __restrict__ queries, const float* __restrict__ values,
    const int*   __restrict__ valid_lens,
    const float* __restrict__ Wq, const float* __restrict__ wv,
    float* __restrict__ out)
{
    __shared__ float sqrow[DD];
    __shared__ float sqh2[HN];   // (q-proj) * 2*log2(e)
    __shared__ float swv2[HN];   // 2 * wv
    __shared__ float sc[KN];     // scores -> attn weights
    __shared__ float red[16];
    __shared__ float part[512];
    __shared__ float sbias;      // sum(wv)
    __shared__ float smax, sinv;

    const int q = blockIdx.x, b = blockIdx.y;
    const int tid = threadIdx.x;
    const float TWO_LOG2E = 2.8853900817779268f;  // 2*log2(e)
    const float LOG2E     = 1.4426950408889634f;

    if (tid < DD) sqrow[tid] = queries[(b * QN + q) * DD + tid];
    if (tid >= 128 && tid < 256) swv2[tid - 128] = 2.0f * wv[tid - 128];
    __syncthreads();

    if (tid < HN) {
        float acc = 0.f;
        #pragma unroll 8
        for (int d = 0; d < DD; d++)
            acc = fmaf(sqrow[d], Wq[d * HN + tid], acc);
        sqh2[tid] = acc * TWO_LOG2E;
    } else if (tid == 256) {
        float s = 0.f;
        #pragma unroll 8
        for (int h = 0; h < HN; h++) s += swv2[h];
        sbias = 0.5f * s;
    }
    __syncthreads();

    // ---- phase 1: scores ----
    const int k = tid;                       // 512 threads == 512 keys
    const float* kp = &g_kpt[(b * HN) * KN + k];
    float acc = 0.f;
    #pragma unroll 8
    for (int h = 0; h < HN; h++) {
        float y = fmaf(kp[h * KN], TWO_LOG2E, sqh2[h]); // 2x*log2e
        float e = ex2f(y);                              // e^{2x}
        float r = rcpf(1.0f + e);                       // 1/(1+e^{2x})
        acc = fmaf(swv2[h], r, acc);
    }
    float s = sbias - acc;                              // sum wv*tanh
    if (k >= valid_lens[b]) s = -1000000.0f;

    // ---- masked softmax (block reduce over 512) ----
    float mx = s;
    #pragma unroll
    for (int off = 16; off; off >>= 1)
        mx = fmaxf(mx, __shfl_xor_sync(0xFFFFFFFFu, mx, off));
    if ((tid & 31) == 0) red[tid >> 5] = mx;
    __syncthreads();
    if (tid < 32) {
        float m = (tid < 16) ? red[tid] : -3.4e38f;
        #pragma unroll
        for (int off = 8; off; off >>= 1)
            m = fmaxf(m, __shfl_xor_sync(0xFFFFFFFFu, m, off));
        if (tid == 0) smax = m;
    }
    __syncthreads();

    float p = ex2f((s - smax) * LOG2E);
    float sm = p;
    #pragma unroll
    for (int off = 16; off; off >>= 1)
        sm += __shfl_xor_sync(0xFFFFFFFFu, sm, off);
    if ((tid & 31) == 0) red[tid >> 5] = sm;
    __syncthreads();
    if (tid < 32) {
        float t = (tid < 16) ? red[tid] : 0.f;
        #pragma unroll
        for (int off = 8; off; off >>= 1)
            t += __shfl_xor_sync(0xFFFFFFFFu, t, off);
        if (tid == 0) sinv = 1.0f / t;   // exact div, once per block
    }
    __syncthreads();
    sc[k] = p * sinv;
    __syncthreads();

    // ---- phase 2: out = attn @ values, split K into 4 groups ----
    const int v = tid & 127, g = tid >> 7;
    const float* vp = values + (size_t)(b * KN + g * 128) * DD + v;
    float acc2 = 0.f;
    #pragma unroll 8
    for (int kk = 0; kk < 128; kk++)
        acc2 = fmaf(sc[g * 128 + kk], vp[(size_t)kk * DD], acc2);
    part[tid] = acc2;
    __syncthreads();
    if (tid < 128)
        out[(b * QN + q) * DD + tid] =
            part[tid] + part[128 + tid] + part[256 + tid] + part[384 + tid];
}

extern "C" void kernel_launch(void* const* d_in, const int* in_sizes, int n_in,
                              void* d_out, int out_size)
{
    const float* queries = (const float*)d_in[0];
    const float* keys    = (const float*)d_in[1];
    const float* values  = (const float*)d_in[2];
    const int*   vlens   = (const int*)  d_in[3];
    const float* Wq      = (const float*)d_in[4];
    const float* Wk      = (const float*)d_in[5];
    const float* wv      = (const float*)d_in[6];
    float* out = (float*)d_out;

    kproj_kernel<<<dim3(KN / 32, BB), 256>>>(keys, Wk);
    attn_kernel<<<dim3(QN, BB), 512>>>(queries, values, vlens, Wq, wv, out);
}

// round 2
// speedup vs baseline: 1.6311x; 1.6311x over previous
#include <cuda_runtime.h>

#define BB 16
#define QN 128
#define KN 512
#define HN 128
#define DD 128
#define QT 4          // queries per block

// scratch: k_proj transposed  [b][h][k]  (4 MB)
__device__ float g_kpt[BB * HN * KN];

__device__ __forceinline__ float ex2f(float x) {
    float r; asm("ex2.approx.f32 %0, %1;" : "=f"(r) : "f"(x)); return r;
}
__device__ __forceinline__ float tanhf_approx(float x) {
    float r; asm("tanh.approx.f32 %0, %1;" : "=f"(r) : "f"(x)); return r;
}

// ---------------------------------------------------------------------------
// Kernel A: g_kpt[b][h][k] = sum_d keys[b][k][d] * Wk[d][h]
// ---------------------------------------------------------------------------
__global__ __launch_bounds__(256) void kproj_kernel(
    const float* __restrict__ keys, const float* __restrict__ Wk)
{
    __shared__ float skeys[32][DD];
    __shared__ float stile[HN][33];

    const int b  = blockIdx.y;
    const int k0 = blockIdx.x * 32;
    const int tid = threadIdx.x;

    for (int i = tid; i < 32 * DD; i += 256) {
        int kk = i >> 7, d = i & 127;
        skeys[kk][d] = keys[(b * KN + k0 + kk) * DD + d];
    }
    __syncthreads();

    for (int o = tid; o < 32 * HN; o += 256) {
        int kk = o >> 7, h = o & 127;
        float acc = 0.f;
        #pragma unroll 8
        for (int d = 0; d < DD; d++)
            acc = fmaf(skeys[kk][d], Wk[d * HN + h], acc);
        stile[h][kk] = acc;
    }
    __syncthreads();

    for (int o = tid; o < HN * 32; o += 256) {
        int h = o >> 5, kk = o & 31;
        g_kpt[(b * HN + h) * KN + k0 + kk] = stile[h][kk];
    }
}

// ---------------------------------------------------------------------------
// Kernel B: one block per (b, 4-query tile). 512 threads (one per key).
// ---------------------------------------------------------------------------
__global__ __launch_bounds__(512) void attn_kernel(
    const float* __restrict__ queries, const float* __restrict__ values,
    const int*   __restrict__ valid_lens,
    const float* __restrict__ Wq, const float* __restrict__ wv,
    float* __restrict__ out)
{
    __shared__ float sqh[QT][HN];        // q-projections
    __shared__ float swv[HN];
    __shared__ float sc[QT][KN];         // attn weights
    __shared__ float part[QT * 512];     // also staging for q rows
    __shared__ float redv[QT][16];
    __shared__ float smax[QT], sinv[QT];

    const int q0 = blockIdx.x * QT, b = blockIdx.y;
    const int tid = threadIdx.x;
    const float LOG2E = 1.4426950408889634f;

    // phase 0a: stage 4 query rows (into part[]) + wv
    if (tid < QT * DD)
        part[tid] = queries[(b * QN + q0 + (tid >> 7)) * DD + (tid & 127)];
    if (tid >= 512 - HN) swv[tid - (512 - HN)] = wv[tid - (512 - HN)];
    __syncthreads();

    // phase 0b: q-projection, thread = (q, h)
    {
        const int qq = tid >> 7, h = tid & 127;
        const float* qr = &part[qq * DD];
        float acc = 0.f;
        #pragma unroll 8
        for (int d = 0; d < DD; d++)
            acc = fmaf(qr[d], Wq[d * HN + h], acc);
        sqh[qq][h] = acc;
    }
    __syncthreads();

    // phase 1: scores. thread = key k; 4 queries per thread.
    const int k = tid;
    const float* kp = &g_kpt[(b * HN) * KN + k];
    float s0 = 0.f, s1 = 0.f, s2 = 0.f, s3 = 0.f;
    #pragma unroll 8
    for (int h = 0; h < HN; h++) {
        float kv = kp[h * KN];
        float w  = swv[h];
        s0 = fmaf(w, tanhf_approx(kv + sqh[0][h]), s0);
        s1 = fmaf(w, tanhf_approx(kv + sqh[1][h]), s1);
        s2 = fmaf(w, tanhf_approx(kv + sqh[2][h]), s2);
        s3 = fmaf(w, tanhf_approx(kv + sqh[3][h]), s3);
    }
    float s[QT] = {s0, s1, s2, s3};
    if (k >= valid_lens[b]) {
        #pragma unroll
        for (int q = 0; q < QT; q++) s[q] = -1000000.0f;
    }

    // masked softmax: block max per q
    {
        float mx[QT];
        #pragma unroll
        for (int q = 0; q < QT; q++) mx[q] = s[q];
        #pragma unroll
        for (int off = 16; off; off >>= 1)
            #pragma unroll
            for (int q = 0; q < QT; q++)
                mx[q] = fmaxf(mx[q], __shfl_xor_sync(0xFFFFFFFFu, mx[q], off));
        if ((tid & 31) == 0)
            #pragma unroll
            for (int q = 0; q < QT; q++) redv[q][tid >> 5] = mx[q];
    }
    __syncthreads();
    if (tid < 64) {                       // 16 lanes per q, 4 q's in 2 warps
        int q = tid >> 4, w = tid & 15;
        float m = redv[q][w];
        #pragma unroll
        for (int off = 8; off; off >>= 1)
            m = fmaxf(m, __shfl_xor_sync(0xFFFFFFFFu, m, off));
        if (w == 0) smax[q] = m;
    }
    __syncthreads();

    float p[QT];
    {
        float sm[QT];
        #pragma unroll
        for (int q = 0; q < QT; q++) {
            p[q] = ex2f((s[q] - smax[q]) * LOG2E);
            sm[q] = p[q];
        }
        #pragma unroll
        for (int off = 16; off; off >>= 1)
            #pragma unroll
            for (int q = 0; q < QT; q++)
                sm[q] += __shfl_xor_sync(0xFFFFFFFFu, sm[q], off);
        if ((tid & 31) == 0)
            #pragma unroll
            for (int q = 0; q < QT; q++) redv[q][tid >> 5] = sm[q];
    }
    __syncthreads();
    if (tid < 64) {
        int q = tid >> 4, w = tid & 15;
        float t = redv[q][w];
        #pragma unroll
        for (int off = 8; off; off >>= 1)
            t += __shfl_xor_sync(0xFFFFFFFFu, t, off);
        if (w == 0) sinv[q] = 1.0f / t;
    }
    __syncthreads();
    #pragma unroll
    for (int q = 0; q < QT; q++) sc[q][k] = p[q] * sinv[q];
    __syncthreads();

    // phase 2: out = attn @ values. thread = (v, k-group); 4 q accumulators.
    {
        const int v = tid & 127, g = tid >> 7;
        const float* vp = values + (size_t)(b * KN + g * 128) * DD + v;
        float a0 = 0.f, a1 = 0.f, a2 = 0.f, a3 = 0.f;
        #pragma unroll 8
        for (int kk = 0; kk < 128; kk++) {
            float vv = vp[(size_t)kk * DD];
            int ki = g * 128 + kk;
            a0 = fmaf(sc[0][ki], vv, a0);
            a1 = fmaf(sc[1][ki], vv, a1);
            a2 = fmaf(sc[2][ki], vv, a2);
            a3 = fmaf(sc[3][ki], vv, a3);
        }
        part[0 * 512 + tid] = a0;
        part[1 * 512 + tid] = a1;
        part[2 * 512 + tid] = a2;
        part[3 * 512 + tid] = a3;
    }
    __syncthreads();
    {
        const int q = tid >> 7, v = tid & 127;
        const float* pq = &part[q * 512];
        out[(b * QN + q0 + q) * DD + v] =
            pq[v] + pq[128 + v] + pq[256 + v] + pq[384 + v];
    }
}

extern "C" void kernel_launch(void* const* d_in, const int* in_sizes, int n_in,
                              void* d_out, int out_size)
{
    const float* queries = (const float*)d_in[0];
    const float* keys    = (const float*)d_in[1];
    const float* values  = (const float*)d_in[2];
    const int*   vlens   = (const int*)  d_in[3];
    const float* Wq      = (const float*)d_in[4];
    const float* Wk      = (const float*)d_in[5];
    const float* wv      = (const float*)d_in[6];
    float* out = (float*)d_out;

    kproj_kernel<<<dim3(KN / 32, BB), 256>>>(keys, Wk);
    attn_kernel<<<dim3(QN / QT, BB), 512>>>(queries, values, vlens, Wq, wv, out);
}

// round 3
// speedup vs baseline: 1.9456x; 1.1928x over previous
#include <cuda_runtime.h>

#define BB 16
#define QN 128
#define KN 512
#define HN 128
#define DD 128
#define QT 8

// scratch
__device__ float g_kpt[BB * HN * KN];   // k-proj transposed [b][h][k]
__device__ float g_qh [BB * QN * HN];   // q-proj           [b][q][h]

__device__ __forceinline__ float ex2f(float x) {
    float r; asm("ex2.approx.f32 %0, %1;" : "=f"(r) : "f"(x)); return r;
}
__device__ __forceinline__ float tanhf_approx(float x) {
    float r; asm("tanh.approx.f32 %0, %1;" : "=f"(r) : "f"(x)); return r;
}

// ---------------------------------------------------------------------------
// proj_kernel: smem-tiled GEMM for both projections.
//   blockIdx.x < 8  : 64-key tile   -> g_kpt[b][h][k]  (transposed store)
//   blockIdx.x >= 8 : 64-query tile -> g_qh[b][q][h]   (direct store)
// dynamic smem: swt[128][128] (64KB) + srt[128][68] (34.8KB)
// ---------------------------------------------------------------------------
__global__ __launch_bounds__(512) void proj_kernel(
    const float* __restrict__ keys, const float* __restrict__ queries,
    const float* __restrict__ Wk,   const float* __restrict__ Wq)
{
    extern __shared__ float dynsmem[];
    float* swt = dynsmem;                                  // [d][h] 128x128
    float (*srt)[68] = (float(*)[68])(dynsmem + DD * HN);  // [d][r] 128x68

    const int b   = blockIdx.y;
    const int tid = threadIdx.x;
    const bool isQ = blockIdx.x >= (KN / 64);
    const int r0  = (isQ ? (blockIdx.x - KN / 64) : blockIdx.x) * 64;
    const float* W    = isQ ? Wq : Wk;
    const float* rows = isQ ? (queries + (size_t)(b * QN + r0) * DD)
                            : (keys    + (size_t)(b * KN + r0) * DD);

    #pragma unroll
    for (int i = 0; i < 32; i++)
        swt[tid + i * 512] = W[tid + i * 512];
    #pragma unroll
    for (int i = 0; i < 16; i++) {
        int idx = tid + i * 512;
        srt[idx & 127][idx >> 7] = rows[idx];
    }
    __syncthreads();

    if (!isQ) {
        // keys: thread tile = 8 k x 2 h.  kt=tid&7 (8 tiles of 8k), ht=tid>>3 (64 tiles of 2h)
        const int kt = tid & 7, ht = tid >> 3;
        float acc[8][2];
        #pragma unroll
        for (int i = 0; i < 8; i++) { acc[i][0] = 0.f; acc[i][1] = 0.f; }
        #pragma unroll 8
        for (int d = 0; d < DD; d++) {
            const float4* s4 = (const float4*)&srt[d][0];
            float4 ka = s4[kt * 2], kb = s4[kt * 2 + 1];
            float2 hw = ((const float2*)swt)[d * 64 + ht];
            float kvv[8] = {ka.x, ka.y, ka.z, ka.w, kb.x, kb.y, kb.z, kb.w};
            #pragma unroll
            for (int i = 0; i < 8; i++) {
                acc[i][0] = fmaf(kvv[i], hw.x, acc[i][0]);
                acc[i][1] = fmaf(kvv[i], hw.y, acc[i][1]);
            }
        }
        __syncthreads();                    // done reading srt
        #pragma unroll
        for (int j = 0; j < 2; j++)
            #pragma unroll
            for (int i = 0; i < 8; i++)
                srt[ht * 2 + j][kt * 8 + i] = acc[i][j];   // srt reused as [h][k]
        __syncthreads();
        #pragma unroll
        for (int i = 0; i < 4; i++) {
            int t = tid + i * 512;          // 2048 float4
            int h = t >> 4, k4 = t & 15;
            float4 v = *(const float4*)&srt[h][k4 * 4];
            *(float4*)&g_kpt[(size_t)(b * HN + h) * KN + r0 + k4 * 4] = v;
        }
    } else {
        // queries: thread tile = 2 q x 8 h.  qt=tid>>4 (32 tiles of 2q), ht2=tid&15 (16 tiles of 8h)
        const int qt = tid >> 4, ht2 = tid & 15;
        float acc[2][8];
        #pragma unroll
        for (int j = 0; j < 2; j++)
            #pragma unroll
            for (int i = 0; i < 8; i++) acc[j][i] = 0.f;
        #pragma unroll 8
        for (int d = 0; d < DD; d++) {
            float2 qv = *(const float2*)&srt[d][qt * 2];
            const float4* w4 = (const float4*)swt + d * 32 + ht2 * 2;
            float4 ha = w4[0], hb = w4[1];
            float hv[8] = {ha.x, ha.y, ha.z, ha.w, hb.x, hb.y, hb.z, hb.w};
            #pragma unroll
            for (int i = 0; i < 8; i++) {
                acc[0][i] = fmaf(qv.x, hv[i], acc[0][i]);
                acc[1][i] = fmaf(qv.y, hv[i], acc[1][i]);
            }
        }
        const int h = ht2 * 8;
        #pragma unroll
        for (int j = 0; j < 2; j++) {
            float* op = &g_qh[(size_t)(b * QN + r0 + qt * 2 + j) * HN + h];
            *(float4*)op       = make_float4(acc[j][0], acc[j][1], acc[j][2], acc[j][3]);
            *(float4*)(op + 4) = make_float4(acc[j][4], acc[j][5], acc[j][6], acc[j][7]);
        }
    }
}

// ---------------------------------------------------------------------------
// attn_kernel: one block per (b, 8-query tile). 512 threads (thread = key).
// ---------------------------------------------------------------------------
__global__ __launch_bounds__(512) void attn_kernel(
    const float* __restrict__ values, const int* __restrict__ valid_lens,
    const float* __restrict__ wv, float* __restrict__ out)
{
    __shared__ float sqh[HN][QT];       // 4KB  q-projections, [h][q]
    __shared__ float swv[HN];
    __shared__ float sc[QT][KN];        // 16KB attn weights
    __shared__ float part[QT * 512];    // 16KB split-K partials
    __shared__ float redv[QT][16];
    __shared__ float smax[QT], sinvs[QT];

    const int q0 = blockIdx.x * QT, b = blockIdx.y;
    const int tid = threadIdx.x;
    const float LOG2E = 1.4426950408889634f;

    #pragma unroll
    for (int i = 0; i < 2; i++) {
        int t = tid + i * 512;
        int qq = t >> 7, h = t & 127;
        sqh[h][qq] = g_qh[(size_t)(b * QN + q0 + qq) * HN + h];
    }
    if (tid < HN) swv[tid] = wv[tid];
    __syncthreads();

    // ---- phase 1: scores.  thread = key k, 8 queries per thread ----
    const int k = tid;
    const float* kp = &g_kpt[(size_t)(b * HN) * KN + k];
    const float4* sqh4 = (const float4*)sqh;
    float s[QT];
    #pragma unroll
    for (int q = 0; q < QT; q++) s[q] = 0.f;
    #pragma unroll 4
    for (int h = 0; h < HN; h++) {
        float kv = kp[(size_t)h * KN];
        float w  = swv[h];
        float4 qa = sqh4[2 * h], qb = sqh4[2 * h + 1];
        s[0] = fmaf(w, tanhf_approx(kv + qa.x), s[0]);
        s[1] = fmaf(w, tanhf_approx(kv + qa.y), s[1]);
        s[2] = fmaf(w, tanhf_approx(kv + qa.z), s[2]);
        s[3] = fmaf(w, tanhf_approx(kv + qa.w), s[3]);
        s[4] = fmaf(w, tanhf_approx(kv + qb.x), s[4]);
        s[5] = fmaf(w, tanhf_approx(kv + qb.y), s[5]);
        s[6] = fmaf(w, tanhf_approx(kv + qb.z), s[6]);
        s[7] = fmaf(w, tanhf_approx(kv + qb.w), s[7]);
    }
    if (k >= __ldg(&valid_lens[b])) {
        #pragma unroll
        for (int q = 0; q < QT; q++) s[q] = -1000000.0f;
    }

    // ---- masked softmax over 512 keys, 8 queries ----
    {
        float mx[QT];
        #pragma unroll
        for (int q = 0; q < QT; q++) mx[q] = s[q];
        #pragma unroll
        for (int off = 16; off; off >>= 1)
            #pragma unroll
            for (int q = 0; q < QT; q++)
                mx[q] = fmaxf(mx[q], __shfl_xor_sync(0xFFFFFFFFu, mx[q], off));
        if ((tid & 31) == 0)
            #pragma unroll
            for (int q = 0; q < QT; q++) redv[q][tid >> 5] = mx[q];
    }
    __syncthreads();
    if (tid < 128) {                 // 16 lanes per q, 8 q's
        int q = tid >> 4, w = tid & 15;
        float m = redv[q][w];
        #pragma unroll
        for (int off = 8; off; off >>= 1)
            m = fmaxf(m, __shfl_xor_sync(0xFFFFFFFFu, m, off));
        if (w == 0) smax[q] = m;
    }
    __syncthreads();

    float p[QT];
    {
        float sm[QT];
        #pragma unroll
        for (int q = 0; q < QT; q++) {
            p[q] = ex2f((s[q] - smax[q]) * LOG2E);
            sm[q] = p[q];
        }
        #pragma unroll
        for (int off = 16; off; off >>= 1)
            #pragma unroll
            for (int q = 0; q < QT; q++)
                sm[q] += __shfl_xor_sync(0xFFFFFFFFu, sm[q], off);
        if ((tid & 31) == 0)
            #pragma unroll
            for (int q = 0; q < QT; q++) redv[q][tid >> 5] = sm[q];
    }
    __syncthreads();
    if (tid < 128) {
        int q = tid >> 4, w = tid & 15;
        float t = redv[q][w];
        #pragma unroll
        for (int off = 8; off; off >>= 1)
            t += __shfl_xor_sync(0xFFFFFFFFu, t, off);
        if (w == 0) sinvs[q] = 1.0f / t;
    }
    __syncthreads();
    #pragma unroll
    for (int q = 0; q < QT; q++) sc[q][k] = p[q] * sinvs[q];
    __syncthreads();

    // ---- phase 2: out = attn @ values.  thread = (v, k-group of 128) ----
    {
        const int v = tid & 127, g = tid >> 7;
        const float* vp = values + (size_t)(b * KN + g * 128) * DD + v;
        float a[QT];
        #pragma unroll
        for (int q = 0; q < QT; q++) a[q] = 0.f;
        #pragma unroll 2
        for (int kk = 0; kk < 128; kk += 4) {
            float v0 = vp[(size_t)(kk + 0) * DD];
            float v1 = vp[(size_t)(kk + 1) * DD];
            float v2 = vp[(size_t)(kk + 2) * DD];
            float v3 = vp[(size_t)(kk + 3) * DD];
            int ki = g * 128 + kk;
            #pragma unroll
            for (int q = 0; q < QT; q++) {
                float4 c = *(const float4*)&sc[q][ki];
                a[q] = fmaf(c.x, v0, a[q]);
                a[q] = fmaf(c.y, v1, a[q]);
                a[q] = fmaf(c.z, v2, a[q]);
                a[q] = fmaf(c.w, v3, a[q]);
            }
        }
        #pragma unroll
        for (int q = 0; q < QT; q++) part[q * 512 + tid] = a[q];
    }
    __syncthreads();
    #pragma unroll
    for (int i = 0; i < 2; i++) {
        int t = tid + i * 512;
        int q = t >> 7, v = t & 127;
        const float* pq = &part[q * 512];
        out[(size_t)(b * QN + q0 + q) * DD + v] =
            (pq[v] + pq[128 + v]) + (pq[256 + v] + pq[384 + v]);
    }
}

extern "C" void kernel_launch(void* const* d_in, const int* in_sizes, int n_in,
                              void* d_out, int out_size)
{
    const float* queries = (const float*)d_in[0];
    const float* keys    = (const float*)d_in[1];
    const float* values  = (const float*)d_in[2];
    const int*   vlens   = (const int*)  d_in[3];
    const float* Wq      = (const float*)d_in[4];
    const float* Wk      = (const float*)d_in[5];
    const float* wv      = (const float*)d_in[6];
    float* out = (float*)d_out;

    const int proj_smem = (DD * HN + DD * 68) * sizeof(float);   // 100,352 B
    cudaFuncSetAttribute(proj_kernel,
                         cudaFuncAttributeMaxDynamicSharedMemorySize, proj_smem);

    proj_kernel<<<dim3(KN / 64 + QN / 64, BB), 512, proj_smem>>>(keys, queries, Wk, Wq);
    attn_kernel<<<dim3(QN / QT, BB), 512>>>(values, vlens, wv, out);
}

// round 4
// speedup vs baseline: 2.0869x; 1.0727x over previous
#include <cuda_runtime.h>

#define BB 16
#define QN 128
#define KN 512
#define HN 128
#define DD 128
#define QT 8

// scratch
__device__ float g_kpt[BB * HN * KN];   // k-proj transposed [b][h][k]
__device__ float g_qh [BB * QN * HN];   // q-proj           [b][q][h]

__device__ __forceinline__ float ex2f(float x) {
    float r; asm("ex2.approx.f32 %0, %1;" : "=f"(r) : "f"(x)); return r;
}
__device__ __forceinline__ float tanhf_approx(float x) {
    float r; asm("tanh.approx.f32 %0, %1;" : "=f"(r) : "f"(x)); return r;
}

// ---------------------------------------------------------------------------
// proj_kernel: smem-tiled GEMM for both projections (unchanged from R3).
// ---------------------------------------------------------------------------
__global__ __launch_bounds__(512) void proj_kernel(
    const float* __restrict__ keys, const float* __restrict__ queries,
    const float* __restrict__ Wk,   const float* __restrict__ Wq)
{
    extern __shared__ float dynsmem[];
    float* swt = dynsmem;                                  // [d][h] 128x128
    float (*srt)[68] = (float(*)[68])(dynsmem + DD * HN);  // [d][r] 128x68

    const int b   = blockIdx.y;
    const int tid = threadIdx.x;
    const bool isQ = blockIdx.x >= (KN / 64);
    const int r0  = (isQ ? (blockIdx.x - KN / 64) : blockIdx.x) * 64;
    const float* W    = isQ ? Wq : Wk;
    const float* rows = isQ ? (queries + (size_t)(b * QN + r0) * DD)
                            : (keys    + (size_t)(b * KN + r0) * DD);

    #pragma unroll
    for (int i = 0; i < 32; i++)
        swt[tid + i * 512] = W[tid + i * 512];
    #pragma unroll
    for (int i = 0; i < 16; i++) {
        int idx = tid + i * 512;
        srt[idx & 127][idx >> 7] = rows[idx];
    }
    __syncthreads();

    if (!isQ) {
        const int kt = tid & 7, ht = tid >> 3;
        float acc[8][2];
        #pragma unroll
        for (int i = 0; i < 8; i++) { acc[i][0] = 0.f; acc[i][1] = 0.f; }
        #pragma unroll 8
        for (int d = 0; d < DD; d++) {
            const float4* s4 = (const float4*)&srt[d][0];
            float4 ka = s4[kt * 2], kb = s4[kt * 2 + 1];
            float2 hw = ((const float2*)swt)[d * 64 + ht];
            float kvv[8] = {ka.x, ka.y, ka.z, ka.w, kb.x, kb.y, kb.z, kb.w};
            #pragma unroll
            for (int i = 0; i < 8; i++) {
                acc[i][0] = fmaf(kvv[i], hw.x, acc[i][0]);
                acc[i][1] = fmaf(kvv[i], hw.y, acc[i][1]);
            }
        }
        __syncthreads();
        #pragma unroll
        for (int j = 0; j < 2; j++)
            #pragma unroll
            for (int i = 0; i < 8; i++)
                srt[ht * 2 + j][kt * 8 + i] = acc[i][j];
        __syncthreads();
        #pragma unroll
        for (int i = 0; i < 4; i++) {
            int t = tid + i * 512;
            int h = t >> 4, k4 = t & 15;
            float4 v = *(const float4*)&srt[h][k4 * 4];
            *(float4*)&g_kpt[(size_t)(b * HN + h) * KN + r0 + k4 * 4] = v;
        }
    } else {
        const int qt = tid >> 4, ht2 = tid & 15;
        float acc[2][8];
        #pragma unroll
        for (int j = 0; j < 2; j++)
            #pragma unroll
            for (int i = 0; i < 8; i++) acc[j][i] = 0.f;
        #pragma unroll 8
        for (int d = 0; d < DD; d++) {
            float2 qv = *(const float2*)&srt[d][qt * 2];
            const float4* w4 = (const float4*)swt + d * 32 + ht2 * 2;
            float4 ha = w4[0], hb = w4[1];
            float hv[8] = {ha.x, ha.y, ha.z, ha.w, hb.x, hb.y, hb.z, hb.w};
            #pragma unroll
            for (int i = 0; i < 8; i++) {
                acc[0][i] = fmaf(qv.x, hv[i], acc[0][i]);
                acc[1][i] = fmaf(qv.y, hv[i], acc[1][i]);
            }
        }
        const int h = ht2 * 8;
        #pragma unroll
        for (int j = 0; j < 2; j++) {
            float* op = &g_qh[(size_t)(b * QN + r0 + qt * 2 + j) * HN + h];
            *(float4*)op       = make_float4(acc[j][0], acc[j][1], acc[j][2], acc[j][3]);
            *(float4*)(op + 4) = make_float4(acc[j][4], acc[j][5], acc[j][6], acc[j][7]);
        }
    }
}

// ---------------------------------------------------------------------------
// attn_kernel: one block per (b, 8-query tile). 512 threads (thread = key).
// Phase loops restructured for front-batched LDGs (MLP=8).
// ---------------------------------------------------------------------------
__global__ __launch_bounds__(512) void attn_kernel(
    const float* __restrict__ values, const int* __restrict__ valid_lens,
    const float* __restrict__ wv, float* __restrict__ out)
{
    __shared__ float sqh[HN][QT];       // [h][q] q-projections
    __shared__ float swv[HN];
    __shared__ float sc[QT][KN];        // attn weights
    __shared__ float part[QT * 512];
    __shared__ float redv[QT][16];
    __shared__ float smax[QT], sinvs[QT];

    const int q0 = blockIdx.x * QT, b = blockIdx.y;
    const int tid = threadIdx.x;
    const float LOG2E = 1.4426950408889634f;

    const int vlen = __ldg(&valid_lens[b]);   // hoisted

    #pragma unroll
    for (int i = 0; i < 2; i++) {
        int t = tid + i * 512;
        int qq = t >> 7, h = t & 127;
        sqh[h][qq] = g_qh[(size_t)(b * QN + q0 + qq) * HN + h];
    }
    if (tid < HN) swv[tid] = wv[tid];
    __syncthreads();

    // ---- phase 1: scores. batch 8 kpt loads up-front each group ----
    const int k = tid;
    const float* kp = &g_kpt[(size_t)(b * HN) * KN + k];
    const float4* sqh4 = (const float4*)sqh;
    float s[QT];
    #pragma unroll
    for (int q = 0; q < QT; q++) s[q] = 0.f;

    #pragma unroll 1
    for (int hb = 0; hb < HN; hb += 8) {
        float kv[8];
        #pragma unroll
        for (int j = 0; j < 8; j++)
            kv[j] = kp[(size_t)(hb + j) * KN];
        #pragma unroll
        for (int j = 0; j < 8; j++) {
            const int h = hb + j;
            const float w = swv[h];
            float4 qa = sqh4[2 * h], qb = sqh4[2 * h + 1];
            s[0] = fmaf(w, tanhf_approx(kv[j] + qa.x), s[0]);
            s[1] = fmaf(w, tanhf_approx(kv[j] + qa.y), s[1]);
            s[2] = fmaf(w, tanhf_approx(kv[j] + qa.z), s[2]);
            s[3] = fmaf(w, tanhf_approx(kv[j] + qa.w), s[3]);
            s[4] = fmaf(w, tanhf_approx(kv[j] + qb.x), s[4]);
            s[5] = fmaf(w, tanhf_approx(kv[j] + qb.y), s[5]);
            s[6] = fmaf(w, tanhf_approx(kv[j] + qb.z), s[6]);
            s[7] = fmaf(w, tanhf_approx(kv[j] + qb.w), s[7]);
        }
    }
    if (k >= vlen) {
        #pragma unroll
        for (int q = 0; q < QT; q++) s[q] = -1000000.0f;
    }

    // ---- masked softmax over 512 keys, 8 queries ----
    {
        float mx[QT];
        #pragma unroll
        for (int q = 0; q < QT; q++) mx[q] = s[q];
        #pragma unroll
        for (int off = 16; off; off >>= 1)
            #pragma unroll
            for (int q = 0; q < QT; q++)
                mx[q] = fmaxf(mx[q], __shfl_xor_sync(0xFFFFFFFFu, mx[q], off));
        if ((tid & 31) == 0)
            #pragma unroll
            for (int q = 0; q < QT; q++) redv[q][tid >> 5] = mx[q];
    }
    __syncthreads();
    if (tid < 128) {
        int q = tid >> 4, w = tid & 15;
        float m = redv[q][w];
        #pragma unroll
        for (int off = 8; off; off >>= 1)
            m = fmaxf(m, __shfl_xor_sync(0xFFFFFFFFu, m, off));
        if (w == 0) smax[q] = m;
    }
    __syncthreads();

    float p[QT];
    {
        float sm[QT];
        #pragma unroll
        for (int q = 0; q < QT; q++) {
            p[q] = ex2f((s[q] - smax[q]) * LOG2E);
            sm[q] = p[q];
        }
        #pragma unroll
        for (int off = 16; off; off >>= 1)
            #pragma unroll
            for (int q = 0; q < QT; q++)
                sm[q] += __shfl_xor_sync(0xFFFFFFFFu, sm[q], off);
        if ((tid & 31) == 0)
            #pragma unroll
            for (int q = 0; q < QT; q++) redv[q][tid >> 5] = sm[q];
    }
    __syncthreads();
    if (tid < 128) {
        int q = tid >> 4, w = tid & 15;
        float t = redv[q][w];
        #pragma unroll
        for (int off = 8; off; off >>= 1)
            t += __shfl_xor_sync(0xFFFFFFFFu, t, off);
        if (w == 0) sinvs[q] = 1.0f / t;
    }
    __syncthreads();
    #pragma unroll
    for (int q = 0; q < QT; q++) sc[q][k] = p[q] * sinvs[q];
    __syncthreads();

    // ---- phase 2: out = attn @ values. batch 8 value loads per group ----
    {
        const int v = tid & 127, g = tid >> 7;
        const float* vp = values + (size_t)(b * KN + g * 128) * DD + v;
        float a[QT];
        #pragma unroll
        for (int q = 0; q < QT; q++) a[q] = 0.f;

        #pragma unroll 1
        for (int kk = 0; kk < 128; kk += 8) {
            float vv[8];
            #pragma unroll
            for (int j = 0; j < 8; j++)
                vv[j] = vp[(size_t)(kk + j) * DD];
            const int ki = g * 128 + kk;
            #pragma unroll
            for (int q = 0; q < QT; q++) {
                float4 c0 = *(const float4*)&sc[q][ki];
                float4 c1 = *(const float4*)&sc[q][ki + 4];
                a[q] = fmaf(c0.x, vv[0], a[q]);
                a[q] = fmaf(c0.y, vv[1], a[q]);
                a[q] = fmaf(c0.z, vv[2], a[q]);
                a[q] = fmaf(c0.w, vv[3], a[q]);
                a[q] = fmaf(c1.x, vv[4], a[q]);
                a[q] = fmaf(c1.y, vv[5], a[q]);
                a[q] = fmaf(c1.z, vv[6], a[q]);
                a[q] = fmaf(c1.w, vv[7], a[q]);
            }
        }
        #pragma unroll
        for (int q = 0; q < QT; q++) part[q * 512 + tid] = a[q];
    }
    __syncthreads();
    #pragma unroll
    for (int i = 0; i < 2; i++) {
        int t = tid + i * 512;
        int q = t >> 7, v = t & 127;
        const float* pq = &part[q * 512];
        out[(size_t)(b * QN + q0 + q) * DD + v] =
            (pq[v] + pq[128 + v]) + (pq[256 + v] + pq[384 + v]);
    }
}

extern "C" void kernel_launch(void* const* d_in, const int* in_sizes, int n_in,
                              void* d_out, int out_size)
{
    const float* queries = (const float*)d_in[0];
    const float* keys    = (const float*)d_in[1];
    const float* values  = (const float*)d_in[2];
    const int*   vlens   = (const int*)  d_in[3];
    const float* Wq      = (const float*)d_in[4];
    const float* Wk      = (const float*)d_in[5];
    const float* wv      = (const float*)d_in[6];
    float* out = (float*)d_out;

    const int proj_smem = (DD * HN + DD * 68) * sizeof(float);   // 100,352 B
    cudaFuncSetAttribute(proj_kernel,
                         cudaFuncAttributeMaxDynamicSharedMemorySize, proj_smem);

    proj_kernel<<<dim3(KN / 64 + QN / 64, BB), 512, proj_smem>>>(keys, queries, Wk, Wq);
    attn_kernel<<<dim3(QN / QT, BB), 512>>>(values, vlens, wv, out);
}